// round 1
// baseline (speedup 1.0000x reference)
#include <cuda_runtime.h>
#include <cstdint>

#define EMBED    768
#define HEADS    6
#define HEAD_DIM 256
#define SEQ      128
#define BATCH    512
#define NTOK     (BATCH * SEQ)        // 65536
#define CATD     (HEADS * HEAD_DIM)   // 1536
#define FFN      (4 * EMBED)          // 3072

// ---------------- scratch (device globals; no runtime allocation) ----------------
__device__ float g_h  [(size_t)NTOK * EMBED]; // LN1 output, later reused for LN2 output
__device__ float g_q  [(size_t)NTOK * CATD];  // Q in [B*T, H*D] layout
__device__ float g_k  [(size_t)NTOK * CATD];
__device__ float g_v  [(size_t)NTOK * CATD];
__device__ float g_o  [(size_t)NTOK * CATD];  // attention head outputs, cat layout
__device__ float g_res[(size_t)NTOK * EMBED]; // attn_out (cat@Wo + bo + x)
__device__ float g_mid[(size_t)NTOK * FFN];   // relu(h2@W1 + b1)

// ---------------- LayerNorm: one block per row of 768 ----------------
__global__ __launch_bounds__(256) void layernorm_k(
    const float* __restrict__ x, float* __restrict__ y,
    const float* __restrict__ g, const float* __restrict__ b)
{
    const int row = blockIdx.x;
    const int tid = threadIdx.x;
    const float* xr = x + (size_t)row * EMBED;

    float v0 = xr[tid];
    float v1 = xr[tid + 256];
    float v2 = xr[tid + 512];

    float s = v0 + v1 + v2;
    float q = v0 * v0 + v1 * v1 + v2 * v2;

    #pragma unroll
    for (int o = 16; o; o >>= 1) {
        s += __shfl_xor_sync(0xffffffffu, s, o);
        q += __shfl_xor_sync(0xffffffffu, q, o);
    }
    __shared__ float ss[8], sq[8];
    const int w = tid >> 5, l = tid & 31;
    if (l == 0) { ss[w] = s; sq[w] = q; }
    __syncthreads();
    float S = 0.f, Q = 0.f;
    #pragma unroll
    for (int i = 0; i < 8; i++) { S += ss[i]; Q += sq[i]; }

    const float mu  = S * (1.0f / EMBED);
    const float var = Q * (1.0f / EMBED) - mu * mu;
    const float inv = rsqrtf(var + 1e-5f);

    float* yr = y + (size_t)row * EMBED;
    yr[tid]       = (v0 - mu) * inv * g[tid]       + b[tid];
    yr[tid + 256] = (v1 - mu) * inv * g[tid + 256] + b[tid + 256];
    yr[tid + 512] = (v2 - mu) * inv * g[tid + 512] + b[tid + 512];
}

// ---------------- Tiled SGEMM 128x128x8, 256 threads, 8x8 per thread ----------------
// C[m,n] = sum_k A[m,k] * B[k,n]  (+bias[n]) (relu) (+res[m,n])
// head_cols > 0: B is a stack of [K, head_cols] matrices; tile's column block
// selects the matrix (used for the per-head QKV weights [H, E, D]).
template<bool BIAS, bool RELU, bool RES>
__global__ __launch_bounds__(256) void sgemm128(
    const float* __restrict__ A, const float* __restrict__ B, float* __restrict__ C,
    int M, int N, int K, int lda, int ldb, int ldc, int head_cols,
    const float* __restrict__ bias, const float* __restrict__ res, int ldres)
{
    __shared__ float As[8][128];
    __shared__ float Bs[8][128];

    const int m0 = blockIdx.x * 128;
    const int n0 = blockIdx.y * 128;
    const int tid = threadIdx.x;

    const float* Ap = A + (size_t)m0 * lda;
    const float* Bp;
    int ldbb;
    if (head_cols > 0) {
        const int head = n0 / head_cols;
        Bp = B + (size_t)head * K * head_cols + (n0 % head_cols);
        ldbb = head_cols;
    } else {
        Bp = B + n0;
        ldbb = ldb;
    }
    float* Cp = C + (size_t)m0 * ldc + n0;

    const int arow = tid >> 1;
    const int acol = (tid & 1) * 4;
    const int brow = tid >> 5;
    const int bcol = (tid & 31) * 4;
    const int tr   = (tid >> 4) * 8;
    const int tc   = (tid & 15) * 8;

    float acc[8][8];
    #pragma unroll
    for (int i = 0; i < 8; i++)
        #pragma unroll
        for (int j = 0; j < 8; j++) acc[i][j] = 0.f;

    for (int k0 = 0; k0 < K; k0 += 8) {
        const float4 av = *reinterpret_cast<const float4*>(Ap + (size_t)arow * lda + k0 + acol);
        const float4 bv = *reinterpret_cast<const float4*>(Bp + (size_t)(k0 + brow) * ldbb + bcol);
        As[acol + 0][arow] = av.x;
        As[acol + 1][arow] = av.y;
        As[acol + 2][arow] = av.z;
        As[acol + 3][arow] = av.w;
        *reinterpret_cast<float4*>(&Bs[brow][bcol]) = bv;
        __syncthreads();

        #pragma unroll
        for (int kk = 0; kk < 8; kk++) {
            float ar[8], br[8];
            const float4 t0 = *reinterpret_cast<const float4*>(&As[kk][tr]);
            const float4 t1 = *reinterpret_cast<const float4*>(&As[kk][tr + 4]);
            ar[0] = t0.x; ar[1] = t0.y; ar[2] = t0.z; ar[3] = t0.w;
            ar[4] = t1.x; ar[5] = t1.y; ar[6] = t1.z; ar[7] = t1.w;
            const float4 u0 = *reinterpret_cast<const float4*>(&Bs[kk][tc]);
            const float4 u1 = *reinterpret_cast<const float4*>(&Bs[kk][tc + 4]);
            br[0] = u0.x; br[1] = u0.y; br[2] = u0.z; br[3] = u0.w;
            br[4] = u1.x; br[5] = u1.y; br[6] = u1.z; br[7] = u1.w;
            #pragma unroll
            for (int i = 0; i < 8; i++)
                #pragma unroll
                for (int j = 0; j < 8; j++)
                    acc[i][j] += ar[i] * br[j];
        }
        __syncthreads();
    }

    float bb[8];
    if (BIAS) {
        #pragma unroll
        for (int j = 0; j < 8; j++) bb[j] = bias[n0 + tc + j];
    }

    #pragma unroll
    for (int i = 0; i < 8; i++) {
        #pragma unroll
        for (int j4 = 0; j4 < 2; j4++) {
            float4 cv;
            cv.x = acc[i][j4 * 4 + 0];
            cv.y = acc[i][j4 * 4 + 1];
            cv.z = acc[i][j4 * 4 + 2];
            cv.w = acc[i][j4 * 4 + 3];
            if (BIAS) {
                cv.x += bb[j4 * 4 + 0]; cv.y += bb[j4 * 4 + 1];
                cv.z += bb[j4 * 4 + 2]; cv.w += bb[j4 * 4 + 3];
            }
            if (RELU) {
                cv.x = fmaxf(cv.x, 0.f); cv.y = fmaxf(cv.y, 0.f);
                cv.z = fmaxf(cv.z, 0.f); cv.w = fmaxf(cv.w, 0.f);
            }
            if (RES) {
                const float4 rv = *reinterpret_cast<const float4*>(
                    res + (size_t)(m0 + tr + i) * ldres + n0 + tc + j4 * 4);
                cv.x += rv.x; cv.y += rv.y; cv.z += rv.z; cv.w += rv.w;
            }
            *reinterpret_cast<float4*>(Cp + (size_t)(tr + i) * ldc + tc + j4 * 4) = cv;
        }
    }
}

// ---------------- fused causal attention, one block per (b, h) ----------------
// q,k,v,o are [B*T, H*D] row-major; thread t owns query row t (T == 128 threads).
__global__ __launch_bounds__(128) void attention_k(
    const float* __restrict__ q, const float* __restrict__ k,
    const float* __restrict__ v, float* __restrict__ o)
{
    extern __shared__ float sm[];
    float* sc    = sm;              // [128][129] padded scores
    float* stage = sm + 128 * 129;  // [128][32] K/V chunk staging

    const int bh = blockIdx.x;
    const int b  = bh / HEADS;
    const int h  = bh - b * HEADS;
    const int t  = threadIdx.x;

    const size_t base = (size_t)b * SEQ * CATD + (size_t)h * HEAD_DIM;
    const float* qb = q + base;
    const float* kb = k + base;
    const float* vb = v + base;
    float*       ob = o + base;

    float* scrow = sc + t * 129;

    // ---- scores: sc[t][s] = q[t,:] . k[s,:]  for s <= t ----
    for (int c = 0; c < 8; c++) {
        __syncthreads();
        #pragma unroll
        for (int e = t; e < 128 * 32; e += 128) {
            const int s = e >> 5, j = e & 31;
            stage[e] = kb[(size_t)s * CATD + c * 32 + j];
        }
        __syncthreads();

        float4 qv[8];
        const float4* qp = reinterpret_cast<const float4*>(qb + (size_t)t * CATD + c * 32);
        #pragma unroll
        for (int i = 0; i < 8; i++) qv[i] = qp[i];

        for (int s = 0; s <= t; s++) {
            const float4* kr = reinterpret_cast<const float4*>(stage + s * 32);
            float p = 0.f;
            #pragma unroll
            for (int i = 0; i < 8; i++) {
                const float4 kv = kr[i];
                p += qv[i].x * kv.x + qv[i].y * kv.y + qv[i].z * kv.z + qv[i].w * kv.w;
            }
            if (c == 0) scrow[s] = p;
            else        scrow[s] += p;
        }
    }

    // ---- softmax over s in [0, t] (scale by EMBED^-0.5, faithful to source) ----
    const float scale = 0.03608439182435161f; // 768^-0.5
    float mx = -1e30f;
    for (int s = 0; s <= t; s++) {
        const float vv = scrow[s] * scale;
        scrow[s] = vv;
        mx = fmaxf(mx, vv);
    }
    float sum = 0.f;
    for (int s = 0; s <= t; s++) {
        const float e = __expf(scrow[s] - mx);
        scrow[s] = e;
        sum += e;
    }
    const float r = 1.0f / sum;
    for (int s = 0; s <= t; s++) scrow[s] *= r;

    // ---- out[t,:] = sum_s p[t,s] * v[s,:] ----
    for (int c = 0; c < 8; c++) {
        __syncthreads();
        #pragma unroll
        for (int e = t; e < 128 * 32; e += 128) {
            const int s = e >> 5, j = e & 31;
            stage[e] = vb[(size_t)s * CATD + c * 32 + j];
        }
        __syncthreads();

        float4 acc[8];
        #pragma unroll
        for (int i = 0; i < 8; i++) acc[i] = make_float4(0.f, 0.f, 0.f, 0.f);

        for (int s = 0; s <= t; s++) {
            const float p = scrow[s];
            const float4* vr = reinterpret_cast<const float4*>(stage + s * 32);
            #pragma unroll
            for (int i = 0; i < 8; i++) {
                const float4 vv = vr[i];
                acc[i].x += p * vv.x; acc[i].y += p * vv.y;
                acc[i].z += p * vv.z; acc[i].w += p * vv.w;
            }
        }
        float4* op = reinterpret_cast<float4*>(ob + (size_t)t * CATD + c * 32);
        #pragma unroll
        for (int i = 0; i < 8; i++) op[i] = acc[i];
    }
}

// ---------------- launch ----------------
extern "C" void kernel_launch(void* const* d_in, const int* in_sizes, int n_in,
                              void* d_out, int out_size)
{
    const float* x   = (const float*)d_in[0];
    const float* Wq  = (const float*)d_in[1];
    const float* Wk  = (const float*)d_in[2];
    const float* Wv  = (const float*)d_in[3];
    const float* Wo  = (const float*)d_in[4];
    const float* bo  = (const float*)d_in[5];
    const float* W1  = (const float*)d_in[6];
    const float* b1  = (const float*)d_in[7];
    const float* W2  = (const float*)d_in[8];
    const float* b2  = (const float*)d_in[9];
    const float* g1  = (const float*)d_in[10];
    const float* be1 = (const float*)d_in[11];
    const float* g2  = (const float*)d_in[12];
    const float* be2 = (const float*)d_in[13];
    float* out = (float*)d_out;

    void *ph, *pq, *pk, *pv, *po, *pr, *pm;
    cudaGetSymbolAddress(&ph, g_h);
    cudaGetSymbolAddress(&pq, g_q);
    cudaGetSymbolAddress(&pk, g_k);
    cudaGetSymbolAddress(&pv, g_v);
    cudaGetSymbolAddress(&po, g_o);
    cudaGetSymbolAddress(&pr, g_res);
    cudaGetSymbolAddress(&pm, g_mid);
    float* H = (float*)ph;
    float* Q = (float*)pq;
    float* K = (float*)pk;
    float* V = (float*)pv;
    float* O = (float*)po;
    float* R = (float*)pr;
    float* MID = (float*)pm;

    const int attn_smem = (128 * 129 + 128 * 32) * (int)sizeof(float); // 82432 B
    cudaFuncSetAttribute(attention_k, cudaFuncAttributeMaxDynamicSharedMemorySize, attn_smem);

    // 1) LN1: x -> H
    layernorm_k<<<NTOK, 256>>>(x, H, g1, be1);

    // 2) QKV projections: H [65536,768] x per-head [768,256] -> [65536,1536]
    {
        dim3 grid(NTOK / 128, CATD / 128);
        sgemm128<false, false, false><<<grid, 256>>>(
            H, Wq, Q, NTOK, CATD, EMBED, EMBED, HEAD_DIM, CATD, HEAD_DIM,
            nullptr, nullptr, 0);
        sgemm128<false, false, false><<<grid, 256>>>(
            H, Wk, K, NTOK, CATD, EMBED, EMBED, HEAD_DIM, CATD, HEAD_DIM,
            nullptr, nullptr, 0);
        sgemm128<false, false, false><<<grid, 256>>>(
            H, Wv, V, NTOK, CATD, EMBED, EMBED, HEAD_DIM, CATD, HEAD_DIM,
            nullptr, nullptr, 0);
    }

    // 3) attention per (b,h)
    attention_k<<<BATCH * HEADS, 128, attn_smem>>>(Q, K, V, O);

    // 4) attn_out = O @ Wo + bo + x
    {
        dim3 grid(NTOK / 128, EMBED / 128);
        sgemm128<true, false, true><<<grid, 256>>>(
            O, Wo, R, NTOK, EMBED, CATD, CATD, EMBED, EMBED, 0,
            bo, x, EMBED);
    }

    // 5) LN2: R -> H (reuse)
    layernorm_k<<<NTOK, 256>>>(R, H, g2, be2);

    // 6) MID = relu(H @ W1 + b1)
    {
        dim3 grid(NTOK / 128, FFN / 128);
        sgemm128<true, true, false><<<grid, 256>>>(
            H, W1, MID, NTOK, FFN, EMBED, EMBED, FFN, FFN, 0,
            b1, nullptr, 0);
    }

    // 7) out = MID @ W2 + b2 + R
    {
        dim3 grid(NTOK / 128, EMBED / 128);
        sgemm128<true, false, true><<<grid, 256>>>(
            MID, W2, out, NTOK, EMBED, FFN, FFN, EMBED, EMBED, 0,
            b2, R, EMBED);
    }
}

// round 4
// speedup vs baseline: 3.5489x; 3.5489x over previous
#include <cuda_runtime.h>
#include <cstdint>

#define EMBED    768
#define HEADS    6
#define HEAD_DIM 256
#define SEQ      128
#define BATCH    512
#define NTOK     (BATCH * SEQ)        // 65536
#define CATD     (HEADS * HEAD_DIM)   // 1536
#define FFN      (4 * EMBED)          // 3072

// ================= helpers =================
__device__ __forceinline__ uint32_t f2tf32(float x) {
    uint32_t y;
    asm("cvt.rna.tf32.f32 %0, %1;" : "=r"(y) : "f"(x));
    return y;
}

// m16n8k8 tf32 MMA (sm_80+; legal on base sm_103)
__device__ __forceinline__ void mma16n8k8(float* c, const uint32_t* a, const uint32_t* b) {
    asm volatile(
        "mma.sync.aligned.m16n8k8.row.col.f32.tf32.tf32.f32 "
        "{%0,%1,%2,%3}, {%4,%5,%6,%7}, {%8,%9}, {%0,%1,%2,%3};"
        : "+f"(c[0]), "+f"(c[1]), "+f"(c[2]), "+f"(c[3])
        : "r"(a[0]), "r"(a[1]), "r"(a[2]), "r"(a[3]), "r"(b[0]), "r"(b[1]));
}

// GEMM tiling
#define TILE_NF  128   // output features per tile (blockIdx.x)
#define TILE_TK  256   // tokens per tile (blockIdx.y)
#define KCH      32    // K elements per smem chunk
#define FB_STR   36    // smem row stride in floats (16B-aligned rows, conflict-spread)
#define GEMM_SMEM ((TILE_TK + TILE_NF) * FB_STR * 4)   // 55296 B

// ================= scratch =================
__device__ float g_h  [(size_t)NTOK * EMBED];
__device__ float g_q  [(size_t)NTOK * CATD];
__device__ float g_k  [(size_t)NTOK * CATD];
__device__ float g_v  [(size_t)NTOK * CATD];
__device__ float g_o  [(size_t)NTOK * CATD];
__device__ float g_res[(size_t)NTOK * EMBED];
__device__ float g_mid[(size_t)NTOK * FFN];
__device__ float g_wtq[(size_t)CATD * EMBED];
__device__ float g_wtk[(size_t)CATD * EMBED];
__device__ float g_wtv[(size_t)CATD * EMBED];
__device__ float g_wto[(size_t)EMBED * CATD];
__device__ float g_wt1[(size_t)FFN * EMBED];
__device__ float g_wt2[(size_t)EMBED * FFN];

// ================= transpose: in(k, n) -> out[n][k] =================
// in addressing: addr(k, n) = (n/Dh)*Kdim*Dh + k*Dh + (n%Dh). Plain matrices: Dh = N.
__global__ __launch_bounds__(256) void transpose_k(
    const float* __restrict__ in, float* __restrict__ out, int Kdim, int N, int Dh)
{
    __shared__ float t[32][33];
    const int k0 = blockIdx.y * 32;
    const int n0 = blockIdx.x * 32;
    const int tx = threadIdx.x, ty = threadIdx.y;

    #pragma unroll
    for (int i = 0; i < 4; i++) {
        const int k = k0 + ty + 8 * i;
        const int n = n0 + tx;
        const int h = n / Dh, d = n - h * Dh;
        t[ty + 8 * i][tx] = in[(size_t)h * Kdim * Dh + (size_t)k * Dh + d];
    }
    __syncthreads();
    #pragma unroll
    for (int i = 0; i < 4; i++) {
        out[(size_t)(n0 + ty + 8 * i) * Kdim + k0 + tx] = t[tx][ty + 8 * i];
    }
}

// ================= LayerNorm =================
__global__ __launch_bounds__(256) void layernorm_k(
    const float* __restrict__ x, float* __restrict__ y,
    const float* __restrict__ g, const float* __restrict__ b)
{
    const int row = blockIdx.x;
    const int tid = threadIdx.x;
    const float* xr = x + (size_t)row * EMBED;

    float v0 = xr[tid];
    float v1 = xr[tid + 256];
    float v2 = xr[tid + 512];

    float s = v0 + v1 + v2;
    float q = v0 * v0 + v1 * v1 + v2 * v2;

    #pragma unroll
    for (int o = 16; o; o >>= 1) {
        s += __shfl_xor_sync(0xffffffffu, s, o);
        q += __shfl_xor_sync(0xffffffffu, q, o);
    }
    __shared__ float ss[8], sq[8];
    const int w = tid >> 5, l = tid & 31;
    if (l == 0) { ss[w] = s; sq[w] = q; }
    __syncthreads();
    float S = 0.f, Q = 0.f;
    #pragma unroll
    for (int i = 0; i < 8; i++) { S += ss[i]; Q += sq[i]; }

    const float mu  = S * (1.0f / EMBED);
    const float var = Q * (1.0f / EMBED) - mu * mu;
    const float inv = rsqrtf(var + 1e-5f);

    float* yr = y + (size_t)row * EMBED;
    yr[tid]       = (v0 - mu) * inv * g[tid]       + b[tid];
    yr[tid + 256] = (v1 - mu) * inv * g[tid + 256] + b[tid + 256];
    yr[tid + 512] = (v2 - mu) * inv * g[tid + 512] + b[tid + 512];
}

// ================= GEMM: C[m,n] = sum_k Hm[m,k] * Wt[n,k] (+bias)(relu)(+res) =================
// grid: x = Nout/128 (features), y = NTOK/256 (tokens); block = 256 (8 warps)
// warp wm=wid&3 -> 64-token slab, wn=wid>>2 -> 64-feature slab; 64x64 warp tile.
template<bool BIAS, bool RELU, bool RES>
__global__ __launch_bounds__(256) void gemm_tc(
    const float* __restrict__ Wt,   // [Nout, K]  K-major
    const float* __restrict__ Hm,   // [NTOK, K]
    float* __restrict__ C,          // [NTOK, Nout]
    int K, int Nout,
    const float* __restrict__ bias,
    const float* __restrict__ res)
{
    extern __shared__ char smem[];
    uint32_t* sA = reinterpret_cast<uint32_t*>(smem);   // tokens   [256][36]
    uint32_t* sB = sA + TILE_TK * FB_STR;               // features [128][36]

    const int tid = threadIdx.x;
    const int wid = tid >> 5, lid = tid & 31;
    const int g = lid >> 2, t = lid & 3;
    const int wm = wid & 3;
    const int wn = wid >> 2;

    const int n0 = blockIdx.x * TILE_NF;
    const int m0 = blockIdx.y * TILE_TK;
    const int chunks = K / KCH;

    const float* Ag = Hm + (size_t)m0 * K;   // tokens (MMA A, row-major m x k)
    const float* Bg = Wt + (size_t)n0 * K;   // features (MMA B, col-major k x n)

    float acc[4][8][4];
    #pragma unroll
    for (int i = 0; i < 4; i++)
        #pragma unroll
        for (int j = 0; j < 8; j++)
            #pragma unroll
            for (int r = 0; r < 4; r++) acc[i][j][r] = 0.f;

    float4 pa[8], pb[4];
    #pragma unroll
    for (int i = 0; i < 8; i++) {
        const int idx = tid + 256 * i, row = idx >> 3, q = idx & 7;
        pa[i] = *reinterpret_cast<const float4*>(Ag + (size_t)row * K + q * 4);
    }
    #pragma unroll
    for (int i = 0; i < 4; i++) {
        const int idx = tid + 256 * i, row = idx >> 3, q = idx & 7;
        pb[i] = *reinterpret_cast<const float4*>(Bg + (size_t)row * K + q * 4);
    }

    for (int c = 0; c < chunks; c++) {
        #pragma unroll
        for (int i = 0; i < 8; i++) {
            const int idx = tid + 256 * i, row = idx >> 3, q = idx & 7;
            uint4 w;
            w.x = f2tf32(pa[i].x); w.y = f2tf32(pa[i].y);
            w.z = f2tf32(pa[i].z); w.w = f2tf32(pa[i].w);
            *reinterpret_cast<uint4*>(sA + row * FB_STR + q * 4) = w;
        }
        #pragma unroll
        for (int i = 0; i < 4; i++) {
            const int idx = tid + 256 * i, row = idx >> 3, q = idx & 7;
            uint4 w;
            w.x = f2tf32(pb[i].x); w.y = f2tf32(pb[i].y);
            w.z = f2tf32(pb[i].z); w.w = f2tf32(pb[i].w);
            *reinterpret_cast<uint4*>(sB + row * FB_STR + q * 4) = w;
        }
        __syncthreads();

        if (c + 1 < chunks) {
            const int kofs = (c + 1) * KCH;
            #pragma unroll
            for (int i = 0; i < 8; i++) {
                const int idx = tid + 256 * i, row = idx >> 3, q = idx & 7;
                pa[i] = *reinterpret_cast<const float4*>(Ag + (size_t)row * K + kofs + q * 4);
            }
            #pragma unroll
            for (int i = 0; i < 4; i++) {
                const int idx = tid + 256 * i, row = idx >> 3, q = idx & 7;
                pb[i] = *reinterpret_cast<const float4*>(Bg + (size_t)row * K + kofs + q * 4);
            }
        }

        #pragma unroll
        for (int ks = 0; ks < 4; ks++) {
            const int kb = ks * 8;
            uint32_t af[4][4];
            #pragma unroll
            for (int mt = 0; mt < 4; mt++) {
                const int rb = wm * 64 + mt * 16;
                af[mt][0] = sA[(rb + g)     * FB_STR + kb + t];
                af[mt][1] = sA[(rb + g + 8) * FB_STR + kb + t];
                af[mt][2] = sA[(rb + g)     * FB_STR + kb + t + 4];
                af[mt][3] = sA[(rb + g + 8) * FB_STR + kb + t + 4];
            }
            uint32_t bf[8][2];
            #pragma unroll
            for (int nt = 0; nt < 8; nt++) {
                const int cb = wn * 64 + nt * 8 + g;
                bf[nt][0] = sB[cb * FB_STR + kb + t];
                bf[nt][1] = sB[cb * FB_STR + kb + t + 4];
            }
            #pragma unroll
            for (int mt = 0; mt < 4; mt++)
                #pragma unroll
                for (int nt = 0; nt < 8; nt++)
                    mma16n8k8(acc[mt][nt], af[mt], bf[nt]);
        }
        __syncthreads();
    }

    // epilogue: c0,c1 -> row g, cols 2t,2t+1 ; c2,c3 -> row g+8
    #pragma unroll
    for (int mt = 0; mt < 4; mt++) {
        #pragma unroll
        for (int nt = 0; nt < 8; nt++) {
            const int col = n0 + wn * 64 + nt * 8 + 2 * t;
            float bx = 0.f, by = 0.f;
            if (BIAS) {
                const float2 b2 = *reinterpret_cast<const float2*>(bias + col);
                bx = b2.x; by = b2.y;
            }
            const int r1 = m0 + wm * 64 + mt * 16 + g;
            const int r2 = r1 + 8;

            float2 v1, v2;
            v1.x = acc[mt][nt][0] + bx; v1.y = acc[mt][nt][1] + by;
            v2.x = acc[mt][nt][2] + bx; v2.y = acc[mt][nt][3] + by;
            if (RELU) {
                v1.x = fmaxf(v1.x, 0.f); v1.y = fmaxf(v1.y, 0.f);
                v2.x = fmaxf(v2.x, 0.f); v2.y = fmaxf(v2.y, 0.f);
            }
            if (RES) {
                const float2 r1v = *reinterpret_cast<const float2*>(res + (size_t)r1 * Nout + col);
                const float2 r2v = *reinterpret_cast<const float2*>(res + (size_t)r2 * Nout + col);
                v1.x += r1v.x; v1.y += r1v.y;
                v2.x += r2v.x; v2.y += r2v.y;
            }
            *reinterpret_cast<float2*>(C + (size_t)r1 * Nout + col) = v1;
            *reinterpret_cast<float2*>(C + (size_t)r2 * Nout + col) = v2;
        }
    }
}

// ================= fused causal attention (fp32) =================
__global__ __launch_bounds__(128) void attention_k(
    const float* __restrict__ q, const float* __restrict__ k,
    const float* __restrict__ v, float* __restrict__ o)
{
    extern __shared__ float sm[];
    float* sc    = sm;              // [128][129]
    float* stage = sm + 128 * 129;  // [128][32]

    const int bh = blockIdx.x;
    const int b  = bh / HEADS;
    const int h  = bh - b * HEADS;
    const int t  = threadIdx.x;

    const size_t base = (size_t)b * SEQ * CATD + (size_t)h * HEAD_DIM;
    const float* qb = q + base;
    const float* kb = k + base;
    const float* vb = v + base;
    float*       ob = o + base;

    float* scrow = sc + t * 129;

    for (int c = 0; c < 8; c++) {
        __syncthreads();
        #pragma unroll
        for (int e = t; e < 128 * 32; e += 128) {
            const int s = e >> 5, j = e & 31;
            stage[e] = kb[(size_t)s * CATD + c * 32 + j];
        }
        __syncthreads();

        float4 qv[8];
        const float4* qp = reinterpret_cast<const float4*>(qb + (size_t)t * CATD + c * 32);
        #pragma unroll
        for (int i = 0; i < 8; i++) qv[i] = qp[i];

        for (int s = 0; s <= t; s++) {
            const float4* kr = reinterpret_cast<const float4*>(stage + s * 32);
            float p = 0.f;
            #pragma unroll
            for (int i = 0; i < 8; i++) {
                const float4 kv = kr[i];
                p += qv[i].x * kv.x + qv[i].y * kv.y + qv[i].z * kv.z + qv[i].w * kv.w;
            }
            if (c == 0) scrow[s] = p;
            else        scrow[s] += p;
        }
    }

    const float scale = 0.03608439182435161f; // 768^-0.5
    float mx = -1e30f;
    for (int s = 0; s <= t; s++) {
        const float vv = scrow[s] * scale;
        scrow[s] = vv;
        mx = fmaxf(mx, vv);
    }
    float sum = 0.f;
    for (int s = 0; s <= t; s++) {
        const float e = __expf(scrow[s] - mx);
        scrow[s] = e;
        sum += e;
    }
    const float r = 1.0f / sum;
    for (int s = 0; s <= t; s++) scrow[s] *= r;

    for (int c = 0; c < 8; c++) {
        __syncthreads();
        #pragma unroll
        for (int e = t; e < 128 * 32; e += 128) {
            const int s = e >> 5, j = e & 31;
            stage[e] = vb[(size_t)s * CATD + c * 32 + j];
        }
        __syncthreads();

        float4 acc[8];
        #pragma unroll
        for (int i = 0; i < 8; i++) acc[i] = make_float4(0.f, 0.f, 0.f, 0.f);

        for (int s = 0; s <= t; s++) {
            const float p = scrow[s];
            const float4* vr = reinterpret_cast<const float4*>(stage + s * 32);
            #pragma unroll
            for (int i = 0; i < 8; i++) {
                const float4 vv = vr[i];
                acc[i].x += p * vv.x; acc[i].y += p * vv.y;
                acc[i].z += p * vv.z; acc[i].w += p * vv.w;
            }
        }
        float4* op = reinterpret_cast<float4*>(ob + (size_t)t * CATD + c * 32);
        #pragma unroll
        for (int i = 0; i < 8; i++) op[i] = acc[i];
    }
}

// ================= launch =================
extern "C" void kernel_launch(void* const* d_in, const int* in_sizes, int n_in,
                              void* d_out, int out_size)
{
    const float* x   = (const float*)d_in[0];
    const float* Wq  = (const float*)d_in[1];
    const float* Wk  = (const float*)d_in[2];
    const float* Wv  = (const float*)d_in[3];
    const float* Wo  = (const float*)d_in[4];
    const float* bo  = (const float*)d_in[5];
    const float* W1  = (const float*)d_in[6];
    const float* b1  = (const float*)d_in[7];
    const float* W2  = (const float*)d_in[8];
    const float* b2  = (const float*)d_in[9];
    const float* g1  = (const float*)d_in[10];
    const float* be1 = (const float*)d_in[11];
    const float* g2  = (const float*)d_in[12];
    const float* be2 = (const float*)d_in[13];
    float* out = (float*)d_out;

    void *ph, *pq, *pk, *pv, *po, *pr, *pm;
    void *pwq, *pwk, *pwv, *pwo, *pw1, *pw2;
    cudaGetSymbolAddress(&ph, g_h);
    cudaGetSymbolAddress(&pq, g_q);
    cudaGetSymbolAddress(&pk, g_k);
    cudaGetSymbolAddress(&pv, g_v);
    cudaGetSymbolAddress(&po, g_o);
    cudaGetSymbolAddress(&pr, g_res);
    cudaGetSymbolAddress(&pm, g_mid);
    cudaGetSymbolAddress(&pwq, g_wtq);
    cudaGetSymbolAddress(&pwk, g_wtk);
    cudaGetSymbolAddress(&pwv, g_wtv);
    cudaGetSymbolAddress(&pwo, g_wto);
    cudaGetSymbolAddress(&pw1, g_wt1);
    cudaGetSymbolAddress(&pw2, g_wt2);
    float* H = (float*)ph;  float* Q = (float*)pq;  float* K = (float*)pk;
    float* V = (float*)pv;  float* O = (float*)po;  float* R = (float*)pr;
    float* MID = (float*)pm;
    float* WTQ = (float*)pwq; float* WTK = (float*)pwk; float* WTV = (float*)pwv;
    float* WTO = (float*)pwo; float* WT1 = (float*)pw1; float* WT2 = (float*)pw2;

    cudaFuncSetAttribute(gemm_tc<false, false, false>, cudaFuncAttributeMaxDynamicSharedMemorySize, GEMM_SMEM);
    cudaFuncSetAttribute(gemm_tc<true,  false, true >, cudaFuncAttributeMaxDynamicSharedMemorySize, GEMM_SMEM);
    cudaFuncSetAttribute(gemm_tc<true,  true,  false>, cudaFuncAttributeMaxDynamicSharedMemorySize, GEMM_SMEM);
    const int attn_smem = (128 * 129 + 128 * 32) * (int)sizeof(float);
    cudaFuncSetAttribute(attention_k, cudaFuncAttributeMaxDynamicSharedMemorySize, attn_smem);

    dim3 tt(32, 8);
    transpose_k<<<dim3(CATD / 32, EMBED / 32), tt>>>(Wq, WTQ, EMBED, CATD, HEAD_DIM);
    transpose_k<<<dim3(CATD / 32, EMBED / 32), tt>>>(Wk, WTK, EMBED, CATD, HEAD_DIM);
    transpose_k<<<dim3(CATD / 32, EMBED / 32), tt>>>(Wv, WTV, EMBED, CATD, HEAD_DIM);
    transpose_k<<<dim3(EMBED / 32, CATD / 32), tt>>>(Wo, WTO, CATD, EMBED, EMBED);
    transpose_k<<<dim3(FFN / 32, EMBED / 32),  tt>>>(W1, WT1, EMBED, FFN, FFN);
    transpose_k<<<dim3(EMBED / 32, FFN / 32),  tt>>>(W2, WT2, FFN, EMBED, EMBED);

    layernorm_k<<<NTOK, 256>>>(x, H, g1, be1);

    {
        dim3 grid(CATD / TILE_NF, NTOK / TILE_TK);
        gemm_tc<false, false, false><<<grid, 256, GEMM_SMEM>>>(WTQ, H, Q, EMBED, CATD, nullptr, nullptr);
        gemm_tc<false, false, false><<<grid, 256, GEMM_SMEM>>>(WTK, H, K, EMBED, CATD, nullptr, nullptr);
        gemm_tc<false, false, false><<<grid, 256, GEMM_SMEM>>>(WTV, H, V, EMBED, CATD, nullptr, nullptr);
    }

    attention_k<<<BATCH * HEADS, 128, attn_smem>>>(Q, K, V, O);

    gemm_tc<true, false, true><<<dim3(EMBED / TILE_NF, NTOK / TILE_TK), 256, GEMM_SMEM>>>(
        WTO, O, R, CATD, EMBED, bo, x);

    layernorm_k<<<NTOK, 256>>>(R, H, g2, be2);

    gemm_tc<true, true, false><<<dim3(FFN / TILE_NF, NTOK / TILE_TK), 256, GEMM_SMEM>>>(
        WT1, H, MID, EMBED, FFN, b1, nullptr);

    gemm_tc<true, false, true><<<dim3(EMBED / TILE_NF, NTOK / TILE_TK), 256, GEMM_SMEM>>>(
        WT2, MID, out, FFN, EMBED, b2, R);
}

// round 5
// speedup vs baseline: 5.0739x; 1.4297x over previous
#include <cuda_runtime.h>
#include <cstdint>

#define EMBED    768
#define HEADS    6
#define HEAD_DIM 256
#define SEQ      128
#define BATCH    512
#define NTOK     (BATCH * SEQ)        // 65536
#define CATD     (HEADS * HEAD_DIM)   // 1536
#define FFN      (4 * EMBED)          // 3072

// ================= helpers =================
// pack two floats into f16x2 (lo, hi)
__device__ __forceinline__ uint32_t packh2(float lo, float hi) {
    uint32_t r;
    asm("cvt.rn.f16x2.f32 %0, %1, %2;" : "=r"(r) : "f"(hi), "f"(lo));
    return r;
}

// m16n8k16 fp16 MMA, fp32 accumulate (sm_80+; legal on base sm_103)
__device__ __forceinline__ void mma16816(float* c, const uint32_t* a, const uint32_t* b) {
    asm volatile(
        "mma.sync.aligned.m16n8k16.row.col.f32.f16.f16.f32 "
        "{%0,%1,%2,%3}, {%4,%5,%6,%7}, {%8,%9}, {%0,%1,%2,%3};"
        : "+f"(c[0]), "+f"(c[1]), "+f"(c[2]), "+f"(c[3])
        : "r"(a[0]), "r"(a[1]), "r"(a[2]), "r"(a[3]), "r"(b[0]), "r"(b[1]));
}

// GEMM tiling
#define TILE_NF  128   // output features per tile (blockIdx.x)
#define TILE_TK  256   // tokens per tile (blockIdx.y)
#define KCH      32    // K elements per smem chunk
#define HSTR     40    // smem row stride in halves (80B rows -> conflict-free frag loads)
#define GEMM_SMEM ((TILE_TK + TILE_NF) * HSTR * 2)   // 30720 B

// ================= scratch =================
__device__ float g_h  [(size_t)NTOK * EMBED];
__device__ float g_q  [(size_t)NTOK * CATD];
__device__ float g_k  [(size_t)NTOK * CATD];
__device__ float g_v  [(size_t)NTOK * CATD];
__device__ float g_o  [(size_t)NTOK * CATD];
__device__ float g_res[(size_t)NTOK * EMBED];
__device__ float g_mid[(size_t)NTOK * FFN];
__device__ float g_wtq[(size_t)CATD * EMBED];
__device__ float g_wtk[(size_t)CATD * EMBED];
__device__ float g_wtv[(size_t)CATD * EMBED];
__device__ float g_wto[(size_t)EMBED * CATD];
__device__ float g_wt1[(size_t)FFN * EMBED];
__device__ float g_wt2[(size_t)EMBED * FFN];

// ================= transpose: in(k, n) -> out[n][k] =================
__global__ __launch_bounds__(256) void transpose_k(
    const float* __restrict__ in, float* __restrict__ out, int Kdim, int N, int Dh)
{
    __shared__ float t[32][33];
    const int k0 = blockIdx.y * 32;
    const int n0 = blockIdx.x * 32;
    const int tx = threadIdx.x, ty = threadIdx.y;

    #pragma unroll
    for (int i = 0; i < 4; i++) {
        const int k = k0 + ty + 8 * i;
        const int n = n0 + tx;
        const int h = n / Dh, d = n - h * Dh;
        t[ty + 8 * i][tx] = in[(size_t)h * Kdim * Dh + (size_t)k * Dh + d];
    }
    __syncthreads();
    #pragma unroll
    for (int i = 0; i < 4; i++) {
        out[(size_t)(n0 + ty + 8 * i) * Kdim + k0 + tx] = t[tx][ty + 8 * i];
    }
}

// ================= LayerNorm =================
__global__ __launch_bounds__(256) void layernorm_k(
    const float* __restrict__ x, float* __restrict__ y,
    const float* __restrict__ g, const float* __restrict__ b)
{
    const int row = blockIdx.x;
    const int tid = threadIdx.x;
    const float* xr = x + (size_t)row * EMBED;

    float v0 = xr[tid];
    float v1 = xr[tid + 256];
    float v2 = xr[tid + 512];

    float s = v0 + v1 + v2;
    float q = v0 * v0 + v1 * v1 + v2 * v2;

    #pragma unroll
    for (int o = 16; o; o >>= 1) {
        s += __shfl_xor_sync(0xffffffffu, s, o);
        q += __shfl_xor_sync(0xffffffffu, q, o);
    }
    __shared__ float ss[8], sq[8];
    const int w = tid >> 5, l = tid & 31;
    if (l == 0) { ss[w] = s; sq[w] = q; }
    __syncthreads();
    float S = 0.f, Q = 0.f;
    #pragma unroll
    for (int i = 0; i < 8; i++) { S += ss[i]; Q += sq[i]; }

    const float mu  = S * (1.0f / EMBED);
    const float var = Q * (1.0f / EMBED) - mu * mu;
    const float inv = rsqrtf(var + 1e-5f);

    float* yr = y + (size_t)row * EMBED;
    yr[tid]       = (v0 - mu) * inv * g[tid]       + b[tid];
    yr[tid + 256] = (v1 - mu) * inv * g[tid + 256] + b[tid + 256];
    yr[tid + 512] = (v2 - mu) * inv * g[tid + 512] + b[tid + 512];
}

// ================= GEMM (fp16 tensor): C[m,n] = sum_k Hm[m,k]*Wt[n,k] (+bias)(relu)(+res) =================
// grid: x = Nout/128 (features), y = NTOK/256 (tokens); block = 256 (8 warps)
// warp wm=wid&3 -> 64-token slab, wn=wid>>2 -> 64-feature slab; 64x64 warp tile.
template<bool BIAS, bool RELU, bool RES>
__global__ __launch_bounds__(256) void gemm_tc(
    const float* __restrict__ Wt,   // [Nout, K]  K-major
    const float* __restrict__ Hm,   // [NTOK, K]
    float* __restrict__ C,          // [NTOK, Nout]
    int K, int Nout,
    const float* __restrict__ bias,
    const float* __restrict__ res)
{
    extern __shared__ char smem[];
    uint16_t* sA = reinterpret_cast<uint16_t*>(smem);   // tokens   [256][HSTR] halves
    uint16_t* sB = sA + TILE_TK * HSTR;                 // features [128][HSTR] halves

    const int tid = threadIdx.x;
    const int wid = tid >> 5, lid = tid & 31;
    const int g = lid >> 2, t = lid & 3;
    const int wm = wid & 3;
    const int wn = wid >> 2;

    const int n0 = blockIdx.x * TILE_NF;
    const int m0 = blockIdx.y * TILE_TK;
    const int chunks = K / KCH;

    const float* Ag = Hm + (size_t)m0 * K;   // tokens (MMA A, row-major m x k)
    const float* Bg = Wt + (size_t)n0 * K;   // features (MMA B, col-major k x n)

    float acc[4][8][4];
    #pragma unroll
    for (int i = 0; i < 4; i++)
        #pragma unroll
        for (int j = 0; j < 8; j++)
            #pragma unroll
            for (int r = 0; r < 4; r++) acc[i][j][r] = 0.f;

    float4 pa[8], pb[4];
    #pragma unroll
    for (int i = 0; i < 8; i++) {
        const int idx = tid + 256 * i, row = idx >> 3, q = idx & 7;
        pa[i] = *reinterpret_cast<const float4*>(Ag + (size_t)row * K + q * 4);
    }
    #pragma unroll
    for (int i = 0; i < 4; i++) {
        const int idx = tid + 256 * i, row = idx >> 3, q = idx & 7;
        pb[i] = *reinterpret_cast<const float4*>(Bg + (size_t)row * K + q * 4);
    }

    for (int c = 0; c < chunks; c++) {
        // store current chunk as fp16
        #pragma unroll
        for (int i = 0; i < 8; i++) {
            const int idx = tid + 256 * i, row = idx >> 3, q = idx & 7;
            uint2 w;
            w.x = packh2(pa[i].x, pa[i].y);
            w.y = packh2(pa[i].z, pa[i].w);
            *reinterpret_cast<uint2*>(sA + row * HSTR + q * 4) = w;
        }
        #pragma unroll
        for (int i = 0; i < 4; i++) {
            const int idx = tid + 256 * i, row = idx >> 3, q = idx & 7;
            uint2 w;
            w.x = packh2(pb[i].x, pb[i].y);
            w.y = packh2(pb[i].z, pb[i].w);
            *reinterpret_cast<uint2*>(sB + row * HSTR + q * 4) = w;
        }
        __syncthreads();

        if (c + 1 < chunks) {
            const int kofs = (c + 1) * KCH;
            #pragma unroll
            for (int i = 0; i < 8; i++) {
                const int idx = tid + 256 * i, row = idx >> 3, q = idx & 7;
                pa[i] = *reinterpret_cast<const float4*>(Ag + (size_t)row * K + kofs + q * 4);
            }
            #pragma unroll
            for (int i = 0; i < 4; i++) {
                const int idx = tid + 256 * i, row = idx >> 3, q = idx & 7;
                pb[i] = *reinterpret_cast<const float4*>(Bg + (size_t)row * K + kofs + q * 4);
            }
        }

        #pragma unroll
        for (int ks = 0; ks < 2; ks++) {          // two k16 steps per 32-K chunk
            const int kb = ks * 16;
            uint32_t af[4][4];
            #pragma unroll
            for (int mt = 0; mt < 4; mt++) {
                const int rb = wm * 64 + mt * 16;
                af[mt][0] = *reinterpret_cast<const uint32_t*>(&sA[(rb + g)     * HSTR + kb + 2 * t]);
                af[mt][1] = *reinterpret_cast<const uint32_t*>(&sA[(rb + g + 8) * HSTR + kb + 2 * t]);
                af[mt][2] = *reinterpret_cast<const uint32_t*>(&sA[(rb + g)     * HSTR + kb + 2 * t + 8]);
                af[mt][3] = *reinterpret_cast<const uint32_t*>(&sA[(rb + g + 8) * HSTR + kb + 2 * t + 8]);
            }
            uint32_t bf[8][2];
            #pragma unroll
            for (int nt = 0; nt < 8; nt++) {
                const int cb = wn * 64 + nt * 8 + g;
                bf[nt][0] = *reinterpret_cast<const uint32_t*>(&sB[cb * HSTR + kb + 2 * t]);
                bf[nt][1] = *reinterpret_cast<const uint32_t*>(&sB[cb * HSTR + kb + 2 * t + 8]);
            }
            #pragma unroll
            for (int mt = 0; mt < 4; mt++)
                #pragma unroll
                for (int nt = 0; nt < 8; nt++)
                    mma16816(acc[mt][nt], af[mt], bf[nt]);
        }
        __syncthreads();
    }

    // epilogue: c0,c1 -> row g cols 2t,2t+1 ; c2,c3 -> row g+8
    #pragma unroll
    for (int mt = 0; mt < 4; mt++) {
        #pragma unroll
        for (int nt = 0; nt < 8; nt++) {
            const int col = n0 + wn * 64 + nt * 8 + 2 * t;
            float bx = 0.f, by = 0.f;
            if (BIAS) {
                const float2 b2 = *reinterpret_cast<const float2*>(bias + col);
                bx = b2.x; by = b2.y;
            }
            const int r1 = m0 + wm * 64 + mt * 16 + g;
            const int r2 = r1 + 8;

            float2 v1, v2;
            v1.x = acc[mt][nt][0] + bx; v1.y = acc[mt][nt][1] + by;
            v2.x = acc[mt][nt][2] + bx; v2.y = acc[mt][nt][3] + by;
            if (RELU) {
                v1.x = fmaxf(v1.x, 0.f); v1.y = fmaxf(v1.y, 0.f);
                v2.x = fmaxf(v2.x, 0.f); v2.y = fmaxf(v2.y, 0.f);
            }
            if (RES) {
                const float2 r1v = *reinterpret_cast<const float2*>(res + (size_t)r1 * Nout + col);
                const float2 r2v = *reinterpret_cast<const float2*>(res + (size_t)r2 * Nout + col);
                v1.x += r1v.x; v1.y += r1v.y;
                v2.x += r2v.x; v2.y += r2v.y;
            }
            *reinterpret_cast<float2*>(C + (size_t)r1 * Nout + col) = v1;
            *reinterpret_cast<float2*>(C + (size_t)r2 * Nout + col) = v2;
        }
    }
}

// ================= fused causal attention (fp32) =================
__global__ __launch_bounds__(128) void attention_k(
    const float* __restrict__ q, const float* __restrict__ k,
    const float* __restrict__ v, float* __restrict__ o)
{
    extern __shared__ float sm[];
    float* sc    = sm;              // [128][129]
    float* stage = sm + 128 * 129;  // [128][32]

    const int bh = blockIdx.x;
    const int b  = bh / HEADS;
    const int h  = bh - b * HEADS;
    const int t  = threadIdx.x;

    const size_t base = (size_t)b * SEQ * CATD + (size_t)h * HEAD_DIM;
    const float* qb = q + base;
    const float* kb = k + base;
    const float* vb = v + base;
    float*       ob = o + base;

    float* scrow = sc + t * 129;

    for (int c = 0; c < 8; c++) {
        __syncthreads();
        #pragma unroll
        for (int e = t; e < 128 * 32; e += 128) {
            const int s = e >> 5, j = e & 31;
            stage[e] = kb[(size_t)s * CATD + c * 32 + j];
        }
        __syncthreads();

        float4 qv[8];
        const float4* qp = reinterpret_cast<const float4*>(qb + (size_t)t * CATD + c * 32);
        #pragma unroll
        for (int i = 0; i < 8; i++) qv[i] = qp[i];

        for (int s = 0; s <= t; s++) {
            const float4* kr = reinterpret_cast<const float4*>(stage + s * 32);
            float p = 0.f;
            #pragma unroll
            for (int i = 0; i < 8; i++) {
                const float4 kv = kr[i];
                p += qv[i].x * kv.x + qv[i].y * kv.y + qv[i].z * kv.z + qv[i].w * kv.w;
            }
            if (c == 0) scrow[s] = p;
            else        scrow[s] += p;
        }
    }

    const float scale = 0.03608439182435161f; // 768^-0.5
    float mx = -1e30f;
    for (int s = 0; s <= t; s++) {
        const float vv = scrow[s] * scale;
        scrow[s] = vv;
        mx = fmaxf(mx, vv);
    }
    float sum = 0.f;
    for (int s = 0; s <= t; s++) {
        const float e = __expf(scrow[s] - mx);
        scrow[s] = e;
        sum += e;
    }
    const float r = 1.0f / sum;
    for (int s = 0; s <= t; s++) scrow[s] *= r;

    for (int c = 0; c < 8; c++) {
        __syncthreads();
        #pragma unroll
        for (int e = t; e < 128 * 32; e += 128) {
            const int s = e >> 5, j = e & 31;
            stage[e] = vb[(size_t)s * CATD + c * 32 + j];
        }
        __syncthreads();

        float4 acc[8];
        #pragma unroll
        for (int i = 0; i < 8; i++) acc[i] = make_float4(0.f, 0.f, 0.f, 0.f);

        for (int s = 0; s <= t; s++) {
            const float p = scrow[s];
            const float4* vr = reinterpret_cast<const float4*>(stage + s * 32);
            #pragma unroll
            for (int i = 0; i < 8; i++) {
                const float4 vv = vr[i];
                acc[i].x += p * vv.x; acc[i].y += p * vv.y;
                acc[i].z += p * vv.z; acc[i].w += p * vv.w;
            }
        }
        float4* op = reinterpret_cast<float4*>(ob + (size_t)t * CATD + c * 32);
        #pragma unroll
        for (int i = 0; i < 8; i++) op[i] = acc[i];
    }
}

// ================= launch =================
extern "C" void kernel_launch(void* const* d_in, const int* in_sizes, int n_in,
                              void* d_out, int out_size)
{
    const float* x   = (const float*)d_in[0];
    const float* Wq  = (const float*)d_in[1];
    const float* Wk  = (const float*)d_in[2];
    const float* Wv  = (const float*)d_in[3];
    const float* Wo  = (const float*)d_in[4];
    const float* bo  = (const float*)d_in[5];
    const float* W1  = (const float*)d_in[6];
    const float* b1  = (const float*)d_in[7];
    const float* W2  = (const float*)d_in[8];
    const float* b2  = (const float*)d_in[9];
    const float* g1  = (const float*)d_in[10];
    const float* be1 = (const float*)d_in[11];
    const float* g2  = (const float*)d_in[12];
    const float* be2 = (const float*)d_in[13];
    float* out = (float*)d_out;

    void *ph, *pq, *pk, *pv, *po, *pr, *pm;
    void *pwq, *pwk, *pwv, *pwo, *pw1, *pw2;
    cudaGetSymbolAddress(&ph, g_h);
    cudaGetSymbolAddress(&pq, g_q);
    cudaGetSymbolAddress(&pk, g_k);
    cudaGetSymbolAddress(&pv, g_v);
    cudaGetSymbolAddress(&po, g_o);
    cudaGetSymbolAddress(&pr, g_res);
    cudaGetSymbolAddress(&pm, g_mid);
    cudaGetSymbolAddress(&pwq, g_wtq);
    cudaGetSymbolAddress(&pwk, g_wtk);
    cudaGetSymbolAddress(&pwv, g_wtv);
    cudaGetSymbolAddress(&pwo, g_wto);
    cudaGetSymbolAddress(&pw1, g_wt1);
    cudaGetSymbolAddress(&pw2, g_wt2);
    float* H = (float*)ph;  float* Q = (float*)pq;  float* K = (float*)pk;
    float* V = (float*)pv;  float* O = (float*)po;  float* R = (float*)pr;
    float* MID = (float*)pm;
    float* WTQ = (float*)pwq; float* WTK = (float*)pwk; float* WTV = (float*)pwv;
    float* WTO = (float*)pwo; float* WT1 = (float*)pw1; float* WT2 = (float*)pw2;

    const int attn_smem = (128 * 129 + 128 * 32) * (int)sizeof(float);
    cudaFuncSetAttribute(attention_k, cudaFuncAttributeMaxDynamicSharedMemorySize, attn_smem);

    dim3 tt(32, 8);
    transpose_k<<<dim3(CATD / 32, EMBED / 32), tt>>>(Wq, WTQ, EMBED, CATD, HEAD_DIM);
    transpose_k<<<dim3(CATD / 32, EMBED / 32), tt>>>(Wk, WTK, EMBED, CATD, HEAD_DIM);
    transpose_k<<<dim3(CATD / 32, EMBED / 32), tt>>>(Wv, WTV, EMBED, CATD, HEAD_DIM);
    transpose_k<<<dim3(EMBED / 32, CATD / 32), tt>>>(Wo, WTO, CATD, EMBED, EMBED);
    transpose_k<<<dim3(FFN / 32, EMBED / 32),  tt>>>(W1, WT1, EMBED, FFN, FFN);
    transpose_k<<<dim3(EMBED / 32, FFN / 32),  tt>>>(W2, WT2, FFN, EMBED, EMBED);

    layernorm_k<<<NTOK, 256>>>(x, H, g1, be1);

    {
        dim3 grid(CATD / TILE_NF, NTOK / TILE_TK);
        gemm_tc<false, false, false><<<grid, 256, GEMM_SMEM>>>(WTQ, H, Q, EMBED, CATD, nullptr, nullptr);
        gemm_tc<false, false, false><<<grid, 256, GEMM_SMEM>>>(WTK, H, K, EMBED, CATD, nullptr, nullptr);
        gemm_tc<false, false, false><<<grid, 256, GEMM_SMEM>>>(WTV, H, V, EMBED, CATD, nullptr, nullptr);
    }

    attention_k<<<BATCH * HEADS, 128, attn_smem>>>(Q, K, V, O);

    gemm_tc<true, false, true><<<dim3(EMBED / TILE_NF, NTOK / TILE_TK), 256, GEMM_SMEM>>>(
        WTO, O, R, CATD, EMBED, bo, x);

    layernorm_k<<<NTOK, 256>>>(R, H, g2, be2);

    gemm_tc<true, true, false><<<dim3(FFN / TILE_NF, NTOK / TILE_TK), 256, GEMM_SMEM>>>(
        WT1, H, MID, EMBED, FFN, b1, nullptr);

    gemm_tc<true, false, true><<<dim3(EMBED / TILE_NF, NTOK / TILE_TK), 256, GEMM_SMEM>>>(
        WT2, MID, out, FFN, EMBED, b2, R);
}

// round 6
// speedup vs baseline: 6.5061x; 1.2823x over previous
#include <cuda_runtime.h>
#include <cuda_fp16.h>
#include <cstdint>

#define EMBED    768
#define HEADS    6
#define HEAD_DIM 256
#define SEQ      128
#define BATCH    512
#define NTOK     (BATCH * SEQ)        // 65536
#define CATD     (HEADS * HEAD_DIM)   // 1536
#define QKVD     (3 * CATD)           // 4608
#define FFN      (4 * EMBED)          // 3072

// ================= helpers =================
__device__ __forceinline__ uint32_t packh2(float lo, float hi) {
    uint32_t r;
    asm("cvt.rn.f16x2.f32 %0, %1, %2;" : "=r"(r) : "f"(hi), "f"(lo));
    return r;
}
__device__ __forceinline__ void mma16816(float* c, const uint32_t* a, const uint32_t* b) {
    asm volatile(
        "mma.sync.aligned.m16n8k16.row.col.f32.f16.f16.f32 "
        "{%0,%1,%2,%3}, {%4,%5,%6,%7}, {%8,%9}, {%0,%1,%2,%3};"
        : "+f"(c[0]), "+f"(c[1]), "+f"(c[2]), "+f"(c[3])
        : "r"(a[0]), "r"(a[1]), "r"(a[2]), "r"(a[3]), "r"(b[0]), "r"(b[1]));
}

// GEMM tiling
#define TILE_NF  128
#define TILE_TK  256
#define KCH      32
#define HSTR     40
#define GEMM_SMEM ((TILE_TK + TILE_NF) * HSTR * 2)   // 30720 B

// ================= scratch =================
__device__ __half g_hh  [(size_t)NTOK * EMBED];   // LN output (1 then 2)
__device__ __half g_qkv [(size_t)NTOK * QKVD];    // fused QKV output
__device__ __half g_oh  [(size_t)NTOK * CATD];    // attention output
__device__ float  g_res [(size_t)NTOK * EMBED];   // attn_out (fp32, feeds LN2 + final residual)
__device__ __half g_mid [(size_t)NTOK * FFN];
__device__ __half g_wqkv[(size_t)QKVD * EMBED];   // [Wq^T; Wk^T; Wv^T]
__device__ __half g_wto [(size_t)EMBED * CATD];
__device__ __half g_wt1 [(size_t)FFN * EMBED];
__device__ __half g_wt2 [(size_t)EMBED * FFN];

// ================= transpose: in(k, n) -> out[n][k] (fp16 out) =================
__global__ __launch_bounds__(256) void transpose_k(
    const float* __restrict__ in, __half* __restrict__ out, int Kdim, int N, int Dh)
{
    __shared__ float t[32][33];
    const int k0 = blockIdx.y * 32;
    const int n0 = blockIdx.x * 32;
    const int tx = threadIdx.x, ty = threadIdx.y;

    #pragma unroll
    for (int i = 0; i < 4; i++) {
        const int k = k0 + ty + 8 * i;
        const int n = n0 + tx;
        const int h = n / Dh, d = n - h * Dh;
        t[ty + 8 * i][tx] = in[(size_t)h * Kdim * Dh + (size_t)k * Dh + d];
    }
    __syncthreads();
    #pragma unroll
    for (int i = 0; i < 4; i++) {
        out[(size_t)(n0 + ty + 8 * i) * Kdim + k0 + tx] = __float2half_rn(t[tx][ty + 8 * i]);
    }
}

// ================= LayerNorm (fp32 in -> fp16 out) =================
__global__ __launch_bounds__(256) void layernorm_k(
    const float* __restrict__ x, __half* __restrict__ y,
    const float* __restrict__ g, const float* __restrict__ b)
{
    const int row = blockIdx.x;
    const int tid = threadIdx.x;
    const float* xr = x + (size_t)row * EMBED;

    float v0 = xr[tid];
    float v1 = xr[tid + 256];
    float v2 = xr[tid + 512];

    float s = v0 + v1 + v2;
    float q = v0 * v0 + v1 * v1 + v2 * v2;

    #pragma unroll
    for (int o = 16; o; o >>= 1) {
        s += __shfl_xor_sync(0xffffffffu, s, o);
        q += __shfl_xor_sync(0xffffffffu, q, o);
    }
    __shared__ float ss[8], sq[8];
    const int w = tid >> 5, l = tid & 31;
    if (l == 0) { ss[w] = s; sq[w] = q; }
    __syncthreads();
    float S = 0.f, Q = 0.f;
    #pragma unroll
    for (int i = 0; i < 8; i++) { S += ss[i]; Q += sq[i]; }

    const float mu  = S * (1.0f / EMBED);
    const float var = Q * (1.0f / EMBED) - mu * mu;
    const float inv = rsqrtf(var + 1e-5f);

    __half* yr = y + (size_t)row * EMBED;
    yr[tid]       = __float2half_rn((v0 - mu) * inv * g[tid]       + b[tid]);
    yr[tid + 256] = __float2half_rn((v1 - mu) * inv * g[tid + 256] + b[tid + 256]);
    yr[tid + 512] = __float2half_rn((v2 - mu) * inv * g[tid + 512] + b[tid + 512]);
}

// ================= GEMM (fp16 in): C[m,n] = sum_k Hm[m,k]*Wt[n,k] (+bias)(relu)(+res) =================
template<bool OUT16, bool BIAS, bool RELU, bool RES>
__global__ __launch_bounds__(256) void gemm_tc(
    const __half* __restrict__ Wt,   // [Nout, K]  K-major fp16
    const __half* __restrict__ Hm,   // [NTOK, K]  fp16
    void* __restrict__ Cout,         // fp16 or fp32 [NTOK, Nout]
    int K, int Nout,
    const float* __restrict__ bias,
    const float* __restrict__ res)
{
    extern __shared__ char smem[];
    uint16_t* sA = reinterpret_cast<uint16_t*>(smem);   // tokens   [256][HSTR]
    uint16_t* sB = sA + TILE_TK * HSTR;                 // features [128][HSTR]

    const int tid = threadIdx.x;
    const int wid = tid >> 5, lid = tid & 31;
    const int g = lid >> 2, t = lid & 3;
    const int wm = wid & 3;
    const int wn = wid >> 2;

    const int n0 = blockIdx.x * TILE_NF;
    const int m0 = blockIdx.y * TILE_TK;
    const int chunks = K / KCH;

    const __half* Ag = Hm + (size_t)m0 * K;
    const __half* Bg = Wt + (size_t)n0 * K;

    float acc[4][8][4];
    #pragma unroll
    for (int i = 0; i < 4; i++)
        #pragma unroll
        for (int j = 0; j < 8; j++)
            #pragma unroll
            for (int r = 0; r < 4; r++) acc[i][j][r] = 0.f;

    uint4 pa[4], pb[2];
    #pragma unroll
    for (int i = 0; i < 4; i++) {   // A: 256 rows x 4 uint4/row = 1024
        const int idx = tid + 256 * i, row = idx >> 2, q = idx & 3;
        pa[i] = *reinterpret_cast<const uint4*>(Ag + (size_t)row * K + q * 8);
    }
    #pragma unroll
    for (int i = 0; i < 2; i++) {   // B: 128 rows x 4 uint4/row = 512
        const int idx = tid + 256 * i, row = idx >> 2, q = idx & 3;
        pb[i] = *reinterpret_cast<const uint4*>(Bg + (size_t)row * K + q * 8);
    }

    for (int c = 0; c < chunks; c++) {
        #pragma unroll
        for (int i = 0; i < 4; i++) {
            const int idx = tid + 256 * i, row = idx >> 2, q = idx & 3;
            *reinterpret_cast<uint4*>(sA + row * HSTR + q * 8) = pa[i];
        }
        #pragma unroll
        for (int i = 0; i < 2; i++) {
            const int idx = tid + 256 * i, row = idx >> 2, q = idx & 3;
            *reinterpret_cast<uint4*>(sB + row * HSTR + q * 8) = pb[i];
        }
        __syncthreads();

        if (c + 1 < chunks) {
            const int kofs = (c + 1) * KCH;
            #pragma unroll
            for (int i = 0; i < 4; i++) {
                const int idx = tid + 256 * i, row = idx >> 2, q = idx & 3;
                pa[i] = *reinterpret_cast<const uint4*>(Ag + (size_t)row * K + kofs + q * 8);
            }
            #pragma unroll
            for (int i = 0; i < 2; i++) {
                const int idx = tid + 256 * i, row = idx >> 2, q = idx & 3;
                pb[i] = *reinterpret_cast<const uint4*>(Bg + (size_t)row * K + kofs + q * 8);
            }
        }

        #pragma unroll
        for (int ks = 0; ks < 2; ks++) {
            const int kb = ks * 16;
            uint32_t af[4][4];
            #pragma unroll
            for (int mt = 0; mt < 4; mt++) {
                const int rb = wm * 64 + mt * 16;
                af[mt][0] = *reinterpret_cast<const uint32_t*>(&sA[(rb + g)     * HSTR + kb + 2 * t]);
                af[mt][1] = *reinterpret_cast<const uint32_t*>(&sA[(rb + g + 8) * HSTR + kb + 2 * t]);
                af[mt][2] = *reinterpret_cast<const uint32_t*>(&sA[(rb + g)     * HSTR + kb + 2 * t + 8]);
                af[mt][3] = *reinterpret_cast<const uint32_t*>(&sA[(rb + g + 8) * HSTR + kb + 2 * t + 8]);
            }
            uint32_t bf[8][2];
            #pragma unroll
            for (int nt = 0; nt < 8; nt++) {
                const int cb = wn * 64 + nt * 8 + g;
                bf[nt][0] = *reinterpret_cast<const uint32_t*>(&sB[cb * HSTR + kb + 2 * t]);
                bf[nt][1] = *reinterpret_cast<const uint32_t*>(&sB[cb * HSTR + kb + 2 * t + 8]);
            }
            #pragma unroll
            for (int mt = 0; mt < 4; mt++)
                #pragma unroll
                for (int nt = 0; nt < 8; nt++)
                    mma16816(acc[mt][nt], af[mt], bf[nt]);
        }
        __syncthreads();
    }

    float* C32 = reinterpret_cast<float*>(Cout);
    __half* C16 = reinterpret_cast<__half*>(Cout);

    #pragma unroll
    for (int mt = 0; mt < 4; mt++) {
        #pragma unroll
        for (int nt = 0; nt < 8; nt++) {
            const int col = n0 + wn * 64 + nt * 8 + 2 * t;
            float bx = 0.f, by = 0.f;
            if (BIAS) {
                const float2 b2 = *reinterpret_cast<const float2*>(bias + col);
                bx = b2.x; by = b2.y;
            }
            const int r1 = m0 + wm * 64 + mt * 16 + g;
            const int r2 = r1 + 8;

            float2 v1, v2;
            v1.x = acc[mt][nt][0] + bx; v1.y = acc[mt][nt][1] + by;
            v2.x = acc[mt][nt][2] + bx; v2.y = acc[mt][nt][3] + by;
            if (RELU) {
                v1.x = fmaxf(v1.x, 0.f); v1.y = fmaxf(v1.y, 0.f);
                v2.x = fmaxf(v2.x, 0.f); v2.y = fmaxf(v2.y, 0.f);
            }
            if (RES) {
                const float2 r1v = *reinterpret_cast<const float2*>(res + (size_t)r1 * Nout + col);
                const float2 r2v = *reinterpret_cast<const float2*>(res + (size_t)r2 * Nout + col);
                v1.x += r1v.x; v1.y += r1v.y;
                v2.x += r2v.x; v2.y += r2v.y;
            }
            if (OUT16) {
                *reinterpret_cast<uint32_t*>(C16 + (size_t)r1 * Nout + col) = packh2(v1.x, v1.y);
                *reinterpret_cast<uint32_t*>(C16 + (size_t)r2 * Nout + col) = packh2(v2.x, v2.y);
            } else {
                *reinterpret_cast<float2*>(C32 + (size_t)r1 * Nout + col) = v1;
                *reinterpret_cast<float2*>(C32 + (size_t)r2 * Nout + col) = v2;
            }
        }
    }
}

// ================= tensor-core causal attention =================
// one CTA per (b,h); 256 threads (8 warps: wm=wid&3 -> 32 q-rows, wn=wid>>2)
// smem: sP [128][136] fp16  |  workspace: max(sQ+sK [2][128][72] fp16, sS [128][132] fp32, sVt [64][130] fp16)
#define PSTR 136
#define QSTR 72
#define SSTR 132
#define VSTR 130
#define ATTN_SMEM (128 * PSTR * 2 + 128 * SSTR * 4)   // 34816 + 67584 = 102400

__global__ __launch_bounds__(256) void attention_k(
    const __half* __restrict__ qkv,   // [NTOK][4608]
    __half* __restrict__ o)           // [NTOK][1536]
{
    extern __shared__ char smem[];
    uint16_t* sP = reinterpret_cast<uint16_t*>(smem);
    char* ws = smem + 128 * PSTR * 2;
    uint16_t* sQ = reinterpret_cast<uint16_t*>(ws);
    uint16_t* sK = sQ + 128 * QSTR;
    float*    sS = reinterpret_cast<float*>(ws);
    uint16_t* sVt = reinterpret_cast<uint16_t*>(ws);

    const int tid = threadIdx.x;
    const int wid = tid >> 5, lid = tid & 31;
    const int g = lid >> 2, t = lid & 3;
    const int wm = wid & 3;
    const int wn = wid >> 2;

    const int bh = blockIdx.x;
    const int b  = bh / HEADS;
    const int h  = bh - b * HEADS;

    const __half* qbase = qkv + (size_t)(b * SEQ) * QKVD + h * HEAD_DIM;            // q at off 0
    const __half* kbase = qbase + CATD;
    const __half* vbase = qbase + 2 * CATD;
    __half* obase = o + (size_t)(b * SEQ) * CATD + h * HEAD_DIM;

    // ---- phase 1: S = Q K^T (chunks of 64 over head dim) ----
    float acc[2][8][4];
    #pragma unroll
    for (int i = 0; i < 2; i++)
        #pragma unroll
        for (int j = 0; j < 8; j++)
            #pragma unroll
            for (int r = 0; r < 4; r++) acc[i][j][r] = 0.f;

    for (int c = 0; c < 4; c++) {
        #pragma unroll
        for (int i = 0; i < 4; i++) {   // 128 rows x 8 uint4 = 1024
            const int idx = tid + 256 * i, row = idx >> 3, q = idx & 7;
            *reinterpret_cast<uint4*>(sQ + row * QSTR + q * 8) =
                *reinterpret_cast<const uint4*>(qbase + (size_t)row * QKVD + c * 64 + q * 8);
            *reinterpret_cast<uint4*>(sK + row * QSTR + q * 8) =
                *reinterpret_cast<const uint4*>(kbase + (size_t)row * QKVD + c * 64 + q * 8);
        }
        __syncthreads();

        #pragma unroll
        for (int ks = 0; ks < 4; ks++) {
            const int kb = ks * 16;
            uint32_t af[2][4];
            #pragma unroll
            for (int mt = 0; mt < 2; mt++) {
                const int rb = wm * 32 + mt * 16;
                af[mt][0] = *reinterpret_cast<const uint32_t*>(&sQ[(rb + g)     * QSTR + kb + 2 * t]);
                af[mt][1] = *reinterpret_cast<const uint32_t*>(&sQ[(rb + g + 8) * QSTR + kb + 2 * t]);
                af[mt][2] = *reinterpret_cast<const uint32_t*>(&sQ[(rb + g)     * QSTR + kb + 2 * t + 8]);
                af[mt][3] = *reinterpret_cast<const uint32_t*>(&sQ[(rb + g + 8) * QSTR + kb + 2 * t + 8]);
            }
            #pragma unroll
            for (int nt = 0; nt < 8; nt++) {
                if (wn * 64 + nt * 8 <= wm * 32 + 31) {   // causal tile skip
                    const int cb = wn * 64 + nt * 8 + g;
                    uint32_t bf[2];
                    bf[0] = *reinterpret_cast<const uint32_t*>(&sK[cb * QSTR + kb + 2 * t]);
                    bf[1] = *reinterpret_cast<const uint32_t*>(&sK[cb * QSTR + kb + 2 * t + 8]);
                    #pragma unroll
                    for (int mt = 0; mt < 2; mt++)
                        mma16816(acc[mt][nt], af[mt], bf);
                }
            }
        }
        __syncthreads();
    }

    // ---- phase 2: write scaled S to smem (fp32) ----
    const float scale = 0.03608439182435161f; // 768^-0.5
    #pragma unroll
    for (int mt = 0; mt < 2; mt++) {
        #pragma unroll
        for (int nt = 0; nt < 8; nt++) {
            const int col = wn * 64 + nt * 8 + 2 * t;
            const int r1 = wm * 32 + mt * 16 + g;
            float2 v1, v2;
            v1.x = acc[mt][nt][0] * scale; v1.y = acc[mt][nt][1] * scale;
            v2.x = acc[mt][nt][2] * scale; v2.y = acc[mt][nt][3] * scale;
            *reinterpret_cast<float2*>(sS + (r1)     * SSTR + col) = v1;
            *reinterpret_cast<float2*>(sS + (r1 + 8) * SSTR + col) = v2;
        }
    }
    __syncthreads();

    // ---- phase 3: softmax per row (threads 0..127), P -> fp16 ----
    if (tid < 128) {
        const int r = tid;
        float* row = sS + r * SSTR;
        float mx = row[0];
        for (int s = 1; s <= r; s++) mx = fmaxf(mx, row[s]);
        float sum = 0.f;
        for (int s = 0; s <= r; s++) {
            const float e = __expf(row[s] - mx);
            row[s] = e;
            sum += e;
        }
        const float inv = 1.0f / sum;
        uint16_t* prow = sP + r * PSTR;
        for (int s = 0; s <= r; s++) {
            const __half hv = __float2half_rn(row[s] * inv);
            prow[s] = *reinterpret_cast<const uint16_t*>(&hv);
        }
        for (int s = r + 1; s < 128; s++) prow[s] = 0;
    }
    __syncthreads();

    // ---- phase 4: O = P V (d-chunks of 64); V transposed into smem ----
    for (int c = 0; c < 4; c++) {
        // stage sVt[d][s] = V[s][c*64+d]
        #pragma unroll
        for (int i = 0; i < 16; i++) {    // 4096 half2
            const int id = tid + 256 * i;
            const int s = id >> 5, d2 = id & 31;
            const uint32_t v2 = *reinterpret_cast<const uint32_t*>(
                vbase + (size_t)s * QKVD + c * 64 + 2 * d2);
            sVt[(2 * d2)     * VSTR + s] = (uint16_t)(v2 & 0xffffu);
            sVt[(2 * d2 + 1) * VSTR + s] = (uint16_t)(v2 >> 16);
        }
        __syncthreads();

        float oacc[2][4][4];
        #pragma unroll
        for (int i = 0; i < 2; i++)
            #pragma unroll
            for (int j = 0; j < 4; j++)
                #pragma unroll
                for (int r = 0; r < 4; r++) oacc[i][j][r] = 0.f;

        #pragma unroll
        for (int ks = 0; ks < 8; ks++) {
            if (ks * 16 > wm * 32 + 31) break;   // causal: P cols beyond row range are zero
            const int kb = ks * 16;
            uint32_t af[2][4];
            #pragma unroll
            for (int mt = 0; mt < 2; mt++) {
                const int rb = wm * 32 + mt * 16;
                af[mt][0] = *reinterpret_cast<const uint32_t*>(&sP[(rb + g)     * PSTR + kb + 2 * t]);
                af[mt][1] = *reinterpret_cast<const uint32_t*>(&sP[(rb + g + 8) * PSTR + kb + 2 * t]);
                af[mt][2] = *reinterpret_cast<const uint32_t*>(&sP[(rb + g)     * PSTR + kb + 2 * t + 8]);
                af[mt][3] = *reinterpret_cast<const uint32_t*>(&sP[(rb + g + 8) * PSTR + kb + 2 * t + 8]);
            }
            #pragma unroll
            for (int nt = 0; nt < 4; nt++) {
                const int cb = wn * 32 + nt * 8 + g;
                uint32_t bf[2];
                bf[0] = *reinterpret_cast<const uint32_t*>(&sVt[cb * VSTR + kb + 2 * t]);
                bf[1] = *reinterpret_cast<const uint32_t*>(&sVt[cb * VSTR + kb + 2 * t + 8]);
                #pragma unroll
                for (int mt = 0; mt < 2; mt++)
                    mma16816(oacc[mt][nt], af[mt], bf);
            }
        }

        // write O chunk (fp16)
        #pragma unroll
        for (int mt = 0; mt < 2; mt++) {
            #pragma unroll
            for (int nt = 0; nt < 4; nt++) {
                const int d = c * 64 + wn * 32 + nt * 8 + 2 * t;
                const int r1 = wm * 32 + mt * 16 + g;
                *reinterpret_cast<uint32_t*>(obase + (size_t)r1 * CATD + d) =
                    packh2(oacc[mt][nt][0], oacc[mt][nt][1]);
                *reinterpret_cast<uint32_t*>(obase + (size_t)(r1 + 8) * CATD + d) =
                    packh2(oacc[mt][nt][2], oacc[mt][nt][3]);
            }
        }
        __syncthreads();
    }
}

// ================= launch =================
extern "C" void kernel_launch(void* const* d_in, const int* in_sizes, int n_in,
                              void* d_out, int out_size)
{
    const float* x   = (const float*)d_in[0];
    const float* Wq  = (const float*)d_in[1];
    const float* Wk  = (const float*)d_in[2];
    const float* Wv  = (const float*)d_in[3];
    const float* Wo  = (const float*)d_in[4];
    const float* bo  = (const float*)d_in[5];
    const float* W1  = (const float*)d_in[6];
    const float* b1  = (const float*)d_in[7];
    const float* W2  = (const float*)d_in[8];
    const float* b2  = (const float*)d_in[9];
    const float* g1  = (const float*)d_in[10];
    const float* be1 = (const float*)d_in[11];
    const float* g2  = (const float*)d_in[12];
    const float* be2 = (const float*)d_in[13];
    float* out = (float*)d_out;

    void *phh, *pqkv, *poh, *pres, *pmid, *pwqkv, *pwto, *pwt1, *pwt2;
    cudaGetSymbolAddress(&phh,  g_hh);
    cudaGetSymbolAddress(&pqkv, g_qkv);
    cudaGetSymbolAddress(&poh,  g_oh);
    cudaGetSymbolAddress(&pres, g_res);
    cudaGetSymbolAddress(&pmid, g_mid);
    cudaGetSymbolAddress(&pwqkv, g_wqkv);
    cudaGetSymbolAddress(&pwto, g_wto);
    cudaGetSymbolAddress(&pwt1, g_wt1);
    cudaGetSymbolAddress(&pwt2, g_wt2);
    __half* H    = (__half*)phh;
    __half* QKV  = (__half*)pqkv;
    __half* O    = (__half*)poh;
    float*  R    = (float*)pres;
    __half* MID  = (__half*)pmid;
    __half* WQKV = (__half*)pwqkv;
    __half* WTO  = (__half*)pwto;
    __half* WT1  = (__half*)pwt1;
    __half* WT2  = (__half*)pwt2;

    cudaFuncSetAttribute(attention_k, cudaFuncAttributeMaxDynamicSharedMemorySize, ATTN_SMEM);

    dim3 tt(32, 8);
    // fused QKV weight: rows [0,1536)=Wq^T, [1536,3072)=Wk^T, [3072,4608)=Wv^T
    transpose_k<<<dim3(CATD / 32, EMBED / 32), tt>>>(Wq, WQKV,                        EMBED, CATD, HEAD_DIM);
    transpose_k<<<dim3(CATD / 32, EMBED / 32), tt>>>(Wk, WQKV + (size_t)CATD * EMBED, EMBED, CATD, HEAD_DIM);
    transpose_k<<<dim3(CATD / 32, EMBED / 32), tt>>>(Wv, WQKV + (size_t)2 * CATD * EMBED, EMBED, CATD, HEAD_DIM);
    transpose_k<<<dim3(EMBED / 32, CATD / 32), tt>>>(Wo, WTO, CATD, EMBED, EMBED);
    transpose_k<<<dim3(FFN / 32, EMBED / 32),  tt>>>(W1, WT1, EMBED, FFN, FFN);
    transpose_k<<<dim3(EMBED / 32, FFN / 32),  tt>>>(W2, WT2, FFN, EMBED, EMBED);

    // LN1
    layernorm_k<<<NTOK, 256>>>(x, H, g1, be1);

    // fused QKV projection -> fp16 [NTOK][4608]
    gemm_tc<true, false, false, false><<<dim3(QKVD / TILE_NF, NTOK / TILE_TK), 256, GEMM_SMEM>>>(
        WQKV, H, QKV, EMBED, QKVD, nullptr, nullptr);

    // attention
    attention_k<<<BATCH * HEADS, 256, ATTN_SMEM>>>(QKV, O);

    // attn_out = O @ Wo + bo + x  (fp32)
    gemm_tc<false, true, false, true><<<dim3(EMBED / TILE_NF, NTOK / TILE_TK), 256, GEMM_SMEM>>>(
        WTO, O, R, CATD, EMBED, bo, x);

    // LN2
    layernorm_k<<<NTOK, 256>>>(R, H, g2, be2);

    // MID = relu(H @ W1 + b1)  (fp16)
    gemm_tc<true, true, true, false><<<dim3(FFN / TILE_NF, NTOK / TILE_TK), 256, GEMM_SMEM>>>(
        WT1, H, MID, EMBED, FFN, b1, nullptr);

    // out = MID @ W2 + b2 + R  (fp32)
    gemm_tc<false, true, false, true><<<dim3(EMBED / TILE_NF, NTOK / TILE_TK), 256, GEMM_SMEM>>>(
        WT2, MID, out, FFN, EMBED, b2, R);
}